// round 12
// baseline (speedup 1.0000x reference)
#include <cuda_runtime.h>
#include <cuda_bf16.h>
#include <mma.h>
#include <cstdint>

using namespace nvcuda;

#define MAX_N 100000
#define N_GRAPHS 64
#define FEAT 64
#define MAX_E 1600000

// ---------------- scratch ----------------
__device__ float g_S[MAX_N * FEAT];
__device__ float g_h[MAX_N * FEAT];
__device__ float g_h2[MAX_N * FEAT];
__device__ int   g_deg[MAX_N];
__device__ int   g_rowstart[MAX_N + 1];
__device__ int   g_cursor[MAX_N];
__device__ int   g_srcs[MAX_E];
__device__ int   g_ei64;
__device__ int   g_b64;

// ---------------- zero degree + dtype detection (merged) ----------------
__global__ void zero_detect_kernel(const void* ei, const void* batch, int nE, int nN) {
    int i = blockIdx.x * blockDim.x + threadIdx.x;
    if (i < nN) g_deg[i] = 0;
    if (blockIdx.x == 0 && threadIdx.x < 32) {
        int lane = threadIdx.x;
        const long long* p = (const long long*)ei;
        long long v = p[lane];
        int ok = (v >= 0 && v < (long long)nN);
        unsigned m = __ballot_sync(0xffffffffu, ok);
        int idx = nN / 2 - 1 - lane;
        long long bv = (idx >= 0) ? ((const long long*)batch)[idx] : 0;
        int bok = (bv >= 0 && bv < 64);
        unsigned bm = __ballot_sync(0xffffffffu, bok);
        if (lane == 0) {
            g_ei64 = (m == 0xffffffffu) ? 1 : 0;
            g_b64  = (bm == 0xffffffffu) ? 1 : 0;
        }
    }
}

// ---------------- CSR build: histogram ----------------
__global__ void hist_kernel(const void* __restrict__ ei_v, int nE) {
    int e = blockIdx.x * blockDim.x + threadIdx.x;
    if (e >= nE) return;
    int dst;
    if (g_ei64) dst = (int)((const long long*)ei_v)[(long long)nE + e];
    else        dst = ((const int*)ei_v)[nE + e];
    atomicAdd(&g_deg[dst], 1);
}

// ---------------- single-kernel exclusive scan (1 block, 1024 thr) --------
// Tiles of 4096 elements, register/broadcast carry. Writes rowstart+cursor.
__global__ void scan_one_kernel(int nN, int nE) {
    __shared__ int wsums[32];
    __shared__ int s_carry;
    int t = threadIdx.x;
    int lane = t & 31, w = t >> 5;
    if (t == 0) s_carry = 0;
    __syncthreads();

    for (int base = 0; base < nN; base += 4096) {
        int i0 = base + t * 4;
        int v0 = (i0 + 0 < nN) ? g_deg[i0 + 0] : 0;
        int v1 = (i0 + 1 < nN) ? g_deg[i0 + 1] : 0;
        int v2 = (i0 + 2 < nN) ? g_deg[i0 + 2] : 0;
        int v3 = (i0 + 3 < nN) ? g_deg[i0 + 3] : 0;
        int p1 = v0, p2 = p1 + v1, p3 = p2 + v2;
        int tot = p3 + v3;

        int sc = tot;
        #pragma unroll
        for (int off = 1; off < 32; off <<= 1) {
            int n = __shfl_up_sync(0xffffffffu, sc, off);
            if (lane >= off) sc += n;
        }
        if (lane == 31) wsums[w] = sc;
        __syncthreads();
        if (w == 0) {
            int v = wsums[lane];
            int ss = v;
            #pragma unroll
            for (int off = 1; off < 32; off <<= 1) {
                int n = __shfl_up_sync(0xffffffffu, ss, off);
                if (lane >= off) ss += n;
            }
            wsums[lane] = ss - v;   // exclusive warp offsets
        }
        __syncthreads();

        int excl = s_carry + wsums[w] + (sc - tot);
        if (i0 + 0 < nN) { g_rowstart[i0 + 0] = excl;      g_cursor[i0 + 0] = excl; }
        if (i0 + 1 < nN) { g_rowstart[i0 + 1] = excl + p1; g_cursor[i0 + 1] = excl + p1; }
        if (i0 + 2 < nN) { g_rowstart[i0 + 2] = excl + p2; g_cursor[i0 + 2] = excl + p2; }
        if (i0 + 3 < nN) { g_rowstart[i0 + 3] = excl + p3; g_cursor[i0 + 3] = excl + p3; }
        __syncthreads();
        if (t == 1023) s_carry = excl + tot;
        __syncthreads();
    }
    if (t == 0) g_rowstart[nN] = nE;
}

// ---------------- CSR build: placement ----------------
__global__ void fill_kernel(const void* __restrict__ ei_v, int nE) {
    int e = blockIdx.x * blockDim.x + threadIdx.x;
    if (e >= nE) return;
    int src, dst;
    if (g_ei64) {
        const long long* ei = (const long long*)ei_v;
        src = (int)ei[e];
        dst = (int)ei[(long long)nE + e];
    } else {
        const int* ei = (const int*)ei_v;
        src = ei[e];
        dst = ei[nE + e];
    }
    int pos = atomicAdd(&g_cursor[dst], 1);
    g_srcs[pos] = src;
}

// ---------------- gather-mean (R7 fp32 form — proven wall, keep) ----------
__global__ void gather_kernel(const float* __restrict__ x, int nN, int fromH) {
    int gtid = blockIdx.x * blockDim.x + threadIdx.x;
    int node = gtid >> 5;
    int lane = gtid & 31;
    if (node >= nN) return;
    const float* base = fromH ? (const float*)g_h : x;
    int s = g_rowstart[node];
    int e = g_rowstart[node + 1];
    float ax = 0.f, ay = 0.f;

    for (int b = s; b < e; b += 32) {
        int cnt = min(32, e - b);
        int idxv = (lane < cnt) ? __ldg(&g_srcs[b + lane]) : 0;
        int j = 0;
        for (; j + 4 <= cnt; j += 4) {
            int a0 = __shfl_sync(0xffffffffu, idxv, j);
            int a1 = __shfl_sync(0xffffffffu, idxv, j + 1);
            int a2 = __shfl_sync(0xffffffffu, idxv, j + 2);
            int a3 = __shfl_sync(0xffffffffu, idxv, j + 3);
            float2 v0 = __ldg((const float2*)(base + (size_t)a0 * FEAT) + lane);
            float2 v1 = __ldg((const float2*)(base + (size_t)a1 * FEAT) + lane);
            float2 v2 = __ldg((const float2*)(base + (size_t)a2 * FEAT) + lane);
            float2 v3 = __ldg((const float2*)(base + (size_t)a3 * FEAT) + lane);
            ax += (v0.x + v1.x) + (v2.x + v3.x);
            ay += (v0.y + v1.y) + (v2.y + v3.y);
        }
        for (; j < cnt; j++) {
            int a0 = __shfl_sync(0xffffffffu, idxv, j);
            float2 v0 = __ldg((const float2*)(base + (size_t)a0 * FEAT) + lane);
            ax += v0.x; ay += v0.y;
        }
    }
    float inv = 1.0f / fmaxf((float)(e - s), 1.0f);
    reinterpret_cast<float2*>(g_S)[node * 32 + lane] = make_float2(ax * inv, ay * inv);
}

// ---------------- wmma tf32 fused layer GEMM (64-row tiles, occ=3) --------
// out = relu([S|X](tf32) @ [Wrel;Wroot](tf32) + b), fp32 accumulate.
// Block: 64 rows x 64 cols, 8 warps = 4 row-groups x 2 col-groups;
// each warp 16x32 via 2 tf32 m16n16k8 frags over K=128 (16 k-steps).
#define A_LDF 136
#define B_LDF 68
__global__ void __launch_bounds__(256, 3)
mma_layer(const float* __restrict__ Xin,
          const float* __restrict__ Wrel,
          const float* __restrict__ Wroot,
          const float* __restrict__ bias,
          float* __restrict__ out,
          int nRows) {
    extern __shared__ float dynf[];
    float* sA = dynf;                 // 64*136*4  = 34816B
    float* sB = dynf + 64 * A_LDF;    // 128*68*4  = 34816B
    float* stage = dynf;              // reused post-compute (64*68*4 = 17408B)
    __shared__ float s_bias[64];

    int tid = threadIdx.x;
    int warp = tid >> 5;
    int wr = warp & 3;      // row group (16 rows)
    int wc = warp >> 2;     // col group (32 cols)
    int rowBase = blockIdx.x * 64;

    if (tid < 64) s_bias[tid] = bias[tid];

    // B tile [k][n] (K=128 rows): tf32-rounded
    for (int i = tid; i < 128 * 64; i += 256) {
        int k = i >> 6, n = i & 63;
        float w = (k < 64) ? Wrel[k * 64 + n] : Wroot[(k - 64) * 64 + n];
        sB[k * B_LDF + n] = wmma::__float_to_tf32(w);
    }

    // A tile [r][k] (64 rows, K=128): k<64 from S, k>=64 from X
    for (int i = tid; i < 64 * 64; i += 256) {
        int r = i >> 6, k = i & 63;
        int grow = rowBase + r;
        float vS = 0.f, vX = 0.f;
        if (grow < nRows) {
            vS = g_S[(size_t)grow * 64 + k];
            vX = Xin[(size_t)grow * 64 + k];
        }
        sA[r * A_LDF + k]      = wmma::__float_to_tf32(vS);
        sA[r * A_LDF + 64 + k] = wmma::__float_to_tf32(vX);
    }
    __syncthreads();

    wmma::fragment<wmma::accumulator, 16, 16, 8, float> acc[2];
    #pragma unroll
    for (int j = 0; j < 2; j++) wmma::fill_fragment(acc[j], 0.0f);

    #pragma unroll
    for (int ks = 0; ks < 16; ks++) {
        wmma::fragment<wmma::matrix_a, 16, 16, 8, wmma::precision::tf32, wmma::row_major> aF;
        wmma::load_matrix_sync(aF, sA + (wr * 16) * A_LDF + ks * 8, A_LDF);
        #pragma unroll
        for (int j = 0; j < 2; j++) {
            wmma::fragment<wmma::matrix_b, 16, 16, 8, wmma::precision::tf32, wmma::row_major> bF;
            wmma::load_matrix_sync(bF, sB + (ks * 8) * B_LDF + wc * 32 + j * 16, B_LDF);
            wmma::mma_sync(acc[j], aF, bF, acc[j]);
        }
    }
    __syncthreads();

    #pragma unroll
    for (int j = 0; j < 2; j++)
        wmma::store_matrix_sync(stage + (wr * 16) * 68 + wc * 32 + j * 16, acc[j], 68,
                                wmma::mem_row_major);
    __syncthreads();

    for (int i = tid; i < 64 * 64; i += 256) {
        int r = i >> 6, c = i & 63;
        int grow = rowBase + r;
        if (grow < nRows) {
            float v = stage[r * 68 + c] + s_bias[c];
            out[(size_t)grow * 64 + c] = fmaxf(v, 0.f);
        }
    }
}

// ---------------- head with fused pooling: one block per graph ------------
__device__ __forceinline__ long long batch_at(const void* b, int i, int is64) {
    return is64 ? ((const long long*)b)[i] : (long long)((const int*)b)[i];
}

__global__ void head_pool_kernel(const void* __restrict__ batch, int nRows,
                                 const float* __restrict__ Wh, const float* __restrict__ bh,
                                 const float* __restrict__ Wc, const float* __restrict__ bc,
                                 const float* __restrict__ Wo, const float* __restrict__ bo,
                                 float* __restrict__ out) {
    int g = blockIdx.x;
    int is64 = g_b64;
    int lo = 0, hi = nRows;
    while (lo < hi) { int m = (lo + hi) >> 1; if (batch_at(batch, m, is64) < g) lo = m + 1; else hi = m; }
    int start = lo;
    lo = 0; hi = nRows;
    while (lo < hi) { int m = (lo + hi) >> 1; if (batch_at(batch, m, is64) < g + 1) lo = m + 1; else hi = m; }
    int end = lo;

    int tid = threadIdx.x;
    int feat = tid & 63;
    int rl   = tid >> 6;

    __shared__ float sm[4][64];
    __shared__ float sp[64];
    __shared__ float sh[64];

    float s = 0.f;
    for (int r = start + rl; r < end; r += 4)
        s += g_h2[(long long)r * FEAT + feat];
    sm[rl][feat] = s;
    __syncthreads();
    if (rl == 0) {
        float tot = sm[0][feat] + sm[1][feat] + sm[2][feat] + sm[3][feat];
        sp[feat] = tot / fmaxf((float)(end - start), 1.0f);
    }
    __syncthreads();

    if (tid < 64) {
        int j = tid;
        float ah = bh[j], ac = bc[j];
        #pragma unroll 8
        for (int k = 0; k < 64; k++) {
            float p = sp[k];
            ah += p * Wh[k * 64 + j];
            ac += p * Wc[k * 64 + j];
        }
        sh[j] = ah;
        out[2048 + g * 64 + j] = ah;
        out[2048 + 4096 + g * 64 + j] = ac;
    }
    __syncthreads();

    if (tid < 32) {
        int lane = tid;
        float z = bo[lane];
        #pragma unroll 8
        for (int k = 0; k < 64; k++)
            z += sh[k] * Wo[k * 32 + lane];
        float m = z;
        #pragma unroll
        for (int off = 16; off > 0; off >>= 1)
            m = fmaxf(m, __shfl_xor_sync(0xffffffffu, m, off));
        float e = expf(z - m);
        #pragma unroll
        for (int off = 16; off > 0; off >>= 1)
            e += __shfl_xor_sync(0xffffffffu, e, off);
        out[g * 32 + lane] = z - m - logf(e);
    }
}

// ---------------- launch ----------------
extern "C" void kernel_launch(void* const* d_in, const int* in_sizes, int n_in,
                              void* d_out, int out_size) {
    const float* x     = (const float*)d_in[0];
    const void*  ei    = d_in[1];
    const void*  batch = d_in[2];
    const float* W1    = (const float*)d_in[3];
    const float* root1 = (const float*)d_in[4];
    const float* b1    = (const float*)d_in[5];
    const float* W2    = (const float*)d_in[6];
    const float* root2 = (const float*)d_in[7];
    const float* b2    = (const float*)d_in[8];
    const float* Wh    = (const float*)d_in[9];
    const float* bh    = (const float*)d_in[10];
    const float* Wc    = (const float*)d_in[11];
    const float* bc    = (const float*)d_in[12];
    const float* Wo    = (const float*)d_in[13];
    const float* bo    = (const float*)d_in[14];

    int nN = in_sizes[0] / FEAT;   // 100000
    int nE = in_sizes[1] / 2;      // 1600000

    int eBlocks = (nE + 255) / 256;
    int nBlocks = (nN + 255) / 256;
    int gatherBlocks = (nN * 32 + 255) / 256;
    int mmaBlocks = (nN + 63) / 64;
    size_t dynBytes = (size_t)(64 * A_LDF + 128 * B_LDF) * 4;   // 69632B

    float* h1 = nullptr; float* h2 = nullptr;
    cudaGetSymbolAddress((void**)&h1, g_h);
    cudaGetSymbolAddress((void**)&h2, g_h2);

    cudaFuncSetAttribute(mma_layer, cudaFuncAttributeMaxDynamicSharedMemorySize,
                         (int)dynBytes);

    // CSR build
    zero_detect_kernel<<<nBlocks, 256>>>(ei, batch, nE, nN);
    hist_kernel<<<eBlocks, 256>>>(ei, nE);
    scan_one_kernel<<<1, 1024>>>(nN, nE);
    fill_kernel<<<eBlocks, 256>>>(ei, nE);

    // layer 1
    gather_kernel<<<gatherBlocks, 256>>>(x, nN, 0);
    mma_layer<<<mmaBlocks, 256, dynBytes>>>(x, W1, root1, b1, h1, nN);

    // layer 2
    gather_kernel<<<gatherBlocks, 256>>>(x, nN, 1);
    mma_layer<<<mmaBlocks, 256, dynBytes>>>(h1, W2, root2, b2, h2, nN);

    // pool + heads (fused)
    head_pool_kernel<<<N_GRAPHS, 256>>>(batch, nN, Wh, bh, Wc, bc, Wo, bo,
                                        (float*)d_out);
}

// round 13
// speedup vs baseline: 1.0320x; 1.0320x over previous
#include <cuda_runtime.h>
#include <cuda_bf16.h>
#include <mma.h>
#include <cstdint>

using namespace nvcuda;

#define MAX_N 100000
#define N_GRAPHS 64
#define FEAT 64
#define MAX_E 1600000

// ---------------- scratch ----------------
__device__ float g_S[MAX_N * FEAT];
__device__ float g_h[MAX_N * FEAT];
__device__ float g_h2[MAX_N * FEAT];
__device__ int   g_deg[MAX_N];
__device__ int   g_rowstart[MAX_N + 1];
__device__ int   g_cursor[MAX_N];
__device__ int   g_srcs[MAX_E];
__device__ int   g_ei64;
__device__ int   g_b64;

// ---------------- zero degree + dtype detection (merged) ----------------
__global__ void zero_detect_kernel(const void* ei, const void* batch, int nE, int nN) {
    int i = blockIdx.x * blockDim.x + threadIdx.x;
    if (i < nN) g_deg[i] = 0;
    if (blockIdx.x == 0 && threadIdx.x < 32) {
        int lane = threadIdx.x;
        const long long* p = (const long long*)ei;
        long long v = p[lane];
        int ok = (v >= 0 && v < (long long)nN);
        unsigned m = __ballot_sync(0xffffffffu, ok);
        int idx = nN / 2 - 1 - lane;
        long long bv = (idx >= 0) ? ((const long long*)batch)[idx] : 0;
        int bok = (bv >= 0 && bv < 64);
        unsigned bm = __ballot_sync(0xffffffffu, bok);
        if (lane == 0) {
            g_ei64 = (m == 0xffffffffu) ? 1 : 0;
            g_b64  = (bm == 0xffffffffu) ? 1 : 0;
        }
    }
}

// ---------------- CSR build: histogram ----------------
__global__ void hist_kernel(const void* __restrict__ ei_v, int nE) {
    int e = blockIdx.x * blockDim.x + threadIdx.x;
    if (e >= nE) return;
    int dst;
    if (g_ei64) dst = (int)((const long long*)ei_v)[(long long)nE + e];
    else        dst = ((const int*)ei_v)[nE + e];
    atomicAdd(&g_deg[dst], 1);
}

// ---------------- single-kernel exclusive scan (1 block, 1024 thr) --------
__global__ void scan_one_kernel(int nN, int nE) {
    __shared__ int wsums[32];
    __shared__ int s_carry;
    int t = threadIdx.x;
    int lane = t & 31, w = t >> 5;
    if (t == 0) s_carry = 0;
    __syncthreads();

    for (int base = 0; base < nN; base += 4096) {
        int i0 = base + t * 4;
        int v0 = (i0 + 0 < nN) ? g_deg[i0 + 0] : 0;
        int v1 = (i0 + 1 < nN) ? g_deg[i0 + 1] : 0;
        int v2 = (i0 + 2 < nN) ? g_deg[i0 + 2] : 0;
        int v3 = (i0 + 3 < nN) ? g_deg[i0 + 3] : 0;
        int p1 = v0, p2 = p1 + v1, p3 = p2 + v2;
        int tot = p3 + v3;

        int sc = tot;
        #pragma unroll
        for (int off = 1; off < 32; off <<= 1) {
            int n = __shfl_up_sync(0xffffffffu, sc, off);
            if (lane >= off) sc += n;
        }
        if (lane == 31) wsums[w] = sc;
        __syncthreads();
        if (w == 0) {
            int v = wsums[lane];
            int ss = v;
            #pragma unroll
            for (int off = 1; off < 32; off <<= 1) {
                int n = __shfl_up_sync(0xffffffffu, ss, off);
                if (lane >= off) ss += n;
            }
            wsums[lane] = ss - v;
        }
        __syncthreads();

        int excl = s_carry + wsums[w] + (sc - tot);
        if (i0 + 0 < nN) { g_rowstart[i0 + 0] = excl;      g_cursor[i0 + 0] = excl; }
        if (i0 + 1 < nN) { g_rowstart[i0 + 1] = excl + p1; g_cursor[i0 + 1] = excl + p1; }
        if (i0 + 2 < nN) { g_rowstart[i0 + 2] = excl + p2; g_cursor[i0 + 2] = excl + p2; }
        if (i0 + 3 < nN) { g_rowstart[i0 + 3] = excl + p3; g_cursor[i0 + 3] = excl + p3; }
        __syncthreads();
        if (t == 1023) s_carry = excl + tot;
        __syncthreads();
    }
    if (t == 0) g_rowstart[nN] = nE;
}

// ---------------- CSR build: placement ----------------
__global__ void fill_kernel(const void* __restrict__ ei_v, int nE) {
    int e = blockIdx.x * blockDim.x + threadIdx.x;
    if (e >= nE) return;
    int src, dst;
    if (g_ei64) {
        const long long* ei = (const long long*)ei_v;
        src = (int)ei[e];
        dst = (int)ei[(long long)nE + e];
    } else {
        const int* ei = (const int*)ei_v;
        src = ei[e];
        dst = ei[nE + e];
    }
    int pos = atomicAdd(&g_cursor[dst], 1);
    g_srcs[pos] = src;
}

// ---------------- gather-mean (R7 fp32 form — proven wall, keep) ----------
__global__ void gather_kernel(const float* __restrict__ x, int nN, int fromH) {
    int gtid = blockIdx.x * blockDim.x + threadIdx.x;
    int node = gtid >> 5;
    int lane = gtid & 31;
    if (node >= nN) return;
    const float* base = fromH ? (const float*)g_h : x;
    int s = g_rowstart[node];
    int e = g_rowstart[node + 1];
    float ax = 0.f, ay = 0.f;

    for (int b = s; b < e; b += 32) {
        int cnt = min(32, e - b);
        int idxv = (lane < cnt) ? __ldg(&g_srcs[b + lane]) : 0;
        int j = 0;
        for (; j + 4 <= cnt; j += 4) {
            int a0 = __shfl_sync(0xffffffffu, idxv, j);
            int a1 = __shfl_sync(0xffffffffu, idxv, j + 1);
            int a2 = __shfl_sync(0xffffffffu, idxv, j + 2);
            int a3 = __shfl_sync(0xffffffffu, idxv, j + 3);
            float2 v0 = __ldg((const float2*)(base + (size_t)a0 * FEAT) + lane);
            float2 v1 = __ldg((const float2*)(base + (size_t)a1 * FEAT) + lane);
            float2 v2 = __ldg((const float2*)(base + (size_t)a2 * FEAT) + lane);
            float2 v3 = __ldg((const float2*)(base + (size_t)a3 * FEAT) + lane);
            ax += (v0.x + v1.x) + (v2.x + v3.x);
            ay += (v0.y + v1.y) + (v2.y + v3.y);
        }
        for (; j < cnt; j++) {
            int a0 = __shfl_sync(0xffffffffu, idxv, j);
            float2 v0 = __ldg((const float2*)(base + (size_t)a0 * FEAT) + lane);
            ax += v0.x; ay += v0.y;
        }
    }
    float inv = 1.0f / fmaxf((float)(e - s), 1.0f);
    reinterpret_cast<float2*>(g_S)[node * 32 + lane] = make_float2(ax * inv, ay * inv);
}

// ---------------- wmma tf32 fused layer GEMM (128 rows, K-split, occ=3) ---
// out = relu([S|X](tf32) @ [Wrel;Wroot](tf32) + b), fp32 accumulate.
// Block: 128 rows x 64 cols, 8 warps; warp w -> rows 16w..16w+15, full 64 cols.
// A buffer holds ONE 64-wide K-half at a time (S half, then X half) -> smem
// 71.7KB total -> 3 CTAs/SM. B tile (full K=128) loaded once.
#define A_LDF 72
#define B_LDF 68
__global__ void __launch_bounds__(256, 3)
mma_layer(const float* __restrict__ Xin,
          const float* __restrict__ Wrel,
          const float* __restrict__ Wroot,
          const float* __restrict__ bias,
          float* __restrict__ out,
          int nRows) {
    extern __shared__ float dynf[];
    float* sA = dynf;                 // 128*72*4 = 36864B (one K-half)
    float* sB = dynf + 128 * A_LDF;   // 128*68*4 = 34816B (full K)
    float* stage = dynf;              // reused post-compute (128*68*4)
    __shared__ float s_bias[64];

    int tid = threadIdx.x;
    int warp = tid >> 5;
    int rowBase = blockIdx.x * 128;

    if (tid < 64) s_bias[tid] = bias[tid];

    // B tile [k][n] (K=128 rows): tf32-rounded
    for (int i = tid; i < 128 * 64; i += 256) {
        int k = i >> 6, n = i & 63;
        float w = (k < 64) ? Wrel[k * 64 + n] : Wroot[(k - 64) * 64 + n];
        sB[k * B_LDF + n] = wmma::__float_to_tf32(w);
    }

    wmma::fragment<wmma::accumulator, 16, 16, 8, float> acc[4];
    #pragma unroll
    for (int j = 0; j < 4; j++) wmma::fill_fragment(acc[j], 0.0f);

    #pragma unroll
    for (int h = 0; h < 2; h++) {
        // protect sA against overwrite while some warps still compute
        __syncthreads();
        const float* src = (h == 0) ? (const float*)g_S : Xin;
        for (int i = tid; i < 128 * 64; i += 256) {
            int r = i >> 6, k = i & 63;
            int grow = rowBase + r;
            float v = (grow < nRows) ? src[(size_t)grow * 64 + k] : 0.f;
            sA[r * A_LDF + k] = wmma::__float_to_tf32(v);
        }
        __syncthreads();

        #pragma unroll
        for (int ks = 0; ks < 8; ks++) {
            wmma::fragment<wmma::matrix_a, 16, 16, 8, wmma::precision::tf32, wmma::row_major> aF;
            wmma::load_matrix_sync(aF, sA + (warp * 16) * A_LDF + ks * 8, A_LDF);
            #pragma unroll
            for (int j = 0; j < 4; j++) {
                wmma::fragment<wmma::matrix_b, 16, 16, 8, wmma::precision::tf32, wmma::row_major> bF;
                wmma::load_matrix_sync(bF, sB + (h * 64 + ks * 8) * B_LDF + j * 16, B_LDF);
                wmma::mma_sync(acc[j], aF, bF, acc[j]);
            }
        }
    }
    __syncthreads();

    #pragma unroll
    for (int j = 0; j < 4; j++)
        wmma::store_matrix_sync(stage + (warp * 16) * 68 + j * 16, acc[j], 68,
                                wmma::mem_row_major);
    __syncthreads();

    for (int i = tid; i < 128 * 64; i += 256) {
        int r = i >> 6, c = i & 63;
        int grow = rowBase + r;
        if (grow < nRows) {
            float v = stage[r * 68 + c] + s_bias[c];
            out[(size_t)grow * 64 + c] = fmaxf(v, 0.f);
        }
    }
}

// ---------------- head with fused pooling: one block per graph ------------
__device__ __forceinline__ long long batch_at(const void* b, int i, int is64) {
    return is64 ? ((const long long*)b)[i] : (long long)((const int*)b)[i];
}

__global__ void head_pool_kernel(const void* __restrict__ batch, int nRows,
                                 const float* __restrict__ Wh, const float* __restrict__ bh,
                                 const float* __restrict__ Wc, const float* __restrict__ bc,
                                 const float* __restrict__ Wo, const float* __restrict__ bo,
                                 float* __restrict__ out) {
    int g = blockIdx.x;
    int is64 = g_b64;
    int lo = 0, hi = nRows;
    while (lo < hi) { int m = (lo + hi) >> 1; if (batch_at(batch, m, is64) < g) lo = m + 1; else hi = m; }
    int start = lo;
    lo = 0; hi = nRows;
    while (lo < hi) { int m = (lo + hi) >> 1; if (batch_at(batch, m, is64) < g + 1) lo = m + 1; else hi = m; }
    int end = lo;

    int tid = threadIdx.x;
    int feat = tid & 63;
    int rl   = tid >> 6;

    __shared__ float sm[4][64];
    __shared__ float sp[64];
    __shared__ float sh[64];

    float s = 0.f;
    for (int r = start + rl; r < end; r += 4)
        s += g_h2[(long long)r * FEAT + feat];
    sm[rl][feat] = s;
    __syncthreads();
    if (rl == 0) {
        float tot = sm[0][feat] + sm[1][feat] + sm[2][feat] + sm[3][feat];
        sp[feat] = tot / fmaxf((float)(end - start), 1.0f);
    }
    __syncthreads();

    if (tid < 64) {
        int j = tid;
        float ah = bh[j], ac = bc[j];
        #pragma unroll 8
        for (int k = 0; k < 64; k++) {
            float p = sp[k];
            ah += p * Wh[k * 64 + j];
            ac += p * Wc[k * 64 + j];
        }
        sh[j] = ah;
        out[2048 + g * 64 + j] = ah;
        out[2048 + 4096 + g * 64 + j] = ac;
    }
    __syncthreads();

    if (tid < 32) {
        int lane = tid;
        float z = bo[lane];
        #pragma unroll 8
        for (int k = 0; k < 64; k++)
            z += sh[k] * Wo[k * 32 + lane];
        float m = z;
        #pragma unroll
        for (int off = 16; off > 0; off >>= 1)
            m = fmaxf(m, __shfl_xor_sync(0xffffffffu, m, off));
        float e = expf(z - m);
        #pragma unroll
        for (int off = 16; off > 0; off >>= 1)
            e += __shfl_xor_sync(0xffffffffu, e, off);
        out[g * 32 + lane] = z - m - logf(e);
    }
}

// ---------------- launch ----------------
extern "C" void kernel_launch(void* const* d_in, const int* in_sizes, int n_in,
                              void* d_out, int out_size) {
    const float* x     = (const float*)d_in[0];
    const void*  ei    = d_in[1];
    const void*  batch = d_in[2];
    const float* W1    = (const float*)d_in[3];
    const float* root1 = (const float*)d_in[4];
    const float* b1    = (const float*)d_in[5];
    const float* W2    = (const float*)d_in[6];
    const float* root2 = (const float*)d_in[7];
    const float* b2    = (const float*)d_in[8];
    const float* Wh    = (const float*)d_in[9];
    const float* bh    = (const float*)d_in[10];
    const float* Wc    = (const float*)d_in[11];
    const float* bc    = (const float*)d_in[12];
    const float* Wo    = (const float*)d_in[13];
    const float* bo    = (const float*)d_in[14];

    int nN = in_sizes[0] / FEAT;   // 100000
    int nE = in_sizes[1] / 2;      // 1600000

    int eBlocks = (nE + 255) / 256;
    int nBlocks = (nN + 255) / 256;
    int gatherBlocks = (nN * 32 + 255) / 256;
    int mmaBlocks = (nN + 127) / 128;
    size_t dynBytes = (size_t)(128 * A_LDF + 128 * B_LDF) * 4;   // 71680B

    float* h1 = nullptr; float* h2 = nullptr;
    cudaGetSymbolAddress((void**)&h1, g_h);
    cudaGetSymbolAddress((void**)&h2, g_h2);

    cudaFuncSetAttribute(mma_layer, cudaFuncAttributeMaxDynamicSharedMemorySize,
                         (int)dynBytes);

    // CSR build
    zero_detect_kernel<<<nBlocks, 256>>>(ei, batch, nE, nN);
    hist_kernel<<<eBlocks, 256>>>(ei, nE);
    scan_one_kernel<<<1, 1024>>>(nN, nE);
    fill_kernel<<<eBlocks, 256>>>(ei, nE);

    // layer 1
    gather_kernel<<<gatherBlocks, 256>>>(x, nN, 0);
    mma_layer<<<mmaBlocks, 256, dynBytes>>>(x, W1, root1, b1, h1, nN);

    // layer 2
    gather_kernel<<<gatherBlocks, 256>>>(x, nN, 1);
    mma_layer<<<mmaBlocks, 256, dynBytes>>>(h1, W2, root2, b2, h2, nN);

    // pool + heads (fused)
    head_pool_kernel<<<N_GRAPHS, 256>>>(batch, nN, Wh, bh, Wc, bc, Wo, bo,
                                        (float*)d_out);
}

// round 14
// speedup vs baseline: 1.3493x; 1.3075x over previous
#include <cuda_runtime.h>
#include <cuda_bf16.h>
#include <mma.h>
#include <cstdint>

using namespace nvcuda;

#define MAX_N 100000
#define N_GRAPHS 64
#define FEAT 64
#define MAX_E 1600000

// ---------------- scratch ----------------
__device__ float g_S[MAX_N * FEAT];
__device__ float g_h[MAX_N * FEAT];
__device__ float g_h2[MAX_N * FEAT];
__device__ int   g_deg[MAX_N];
__device__ int   g_rowstart[MAX_N + 1];
__device__ int   g_cursor[MAX_N];
__device__ int   g_srcs[MAX_E];
__device__ int   g_bsum[128];
__device__ int   g_ei64;
__device__ int   g_b64;

// ---------------- zero degree + dtype detection (merged) ----------------
__global__ void zero_detect_kernel(const void* ei, const void* batch, int nE, int nN) {
    int i = blockIdx.x * blockDim.x + threadIdx.x;
    if (i < nN) g_deg[i] = 0;
    if (blockIdx.x == 0 && threadIdx.x < 32) {
        int lane = threadIdx.x;
        const long long* p = (const long long*)ei;
        long long v = p[lane];
        int ok = (v >= 0 && v < (long long)nN);
        unsigned m = __ballot_sync(0xffffffffu, ok);
        int idx = nN / 2 - 1 - lane;
        long long bv = (idx >= 0) ? ((const long long*)batch)[idx] : 0;
        int bok = (bv >= 0 && bv < 64);
        unsigned bm = __ballot_sync(0xffffffffu, bok);
        if (lane == 0) {
            g_ei64 = (m == 0xffffffffu) ? 1 : 0;
            g_b64  = (bm == 0xffffffffu) ? 1 : 0;
        }
    }
}

// ---------------- CSR build: histogram ----------------
__global__ void hist_kernel(const void* __restrict__ ei_v, int nE) {
    int e = blockIdx.x * blockDim.x + threadIdx.x;
    if (e >= nE) return;
    int dst;
    if (g_ei64) dst = (int)((const long long*)ei_v)[(long long)nE + e];
    else        dst = ((const int*)ei_v)[nE + e];
    atomicAdd(&g_deg[dst], 1);
}

// ---------------- scan phase 1: per-1024-block exclusive scan -------------
__global__ void scan_block_kernel(int nN) {
    __shared__ int wsum[8];
    __shared__ int woff[8];
    int blk = blockIdx.x, t = threadIdx.x;
    int base = blk * 1024 + t * 4;
    int v0 = (base + 0 < nN) ? g_deg[base + 0] : 0;
    int v1 = (base + 1 < nN) ? g_deg[base + 1] : 0;
    int v2 = (base + 2 < nN) ? g_deg[base + 2] : 0;
    int v3 = (base + 3 < nN) ? g_deg[base + 3] : 0;
    int i0 = v0, i1 = i0 + v1, i2 = i1 + v2, i3 = i2 + v3;
    int tot = i3;
    int lane = t & 31, w = t >> 5;
    int sc = tot;
    #pragma unroll
    for (int off = 1; off < 32; off <<= 1) {
        int n = __shfl_up_sync(0xffffffffu, sc, off);
        if (lane >= off) sc += n;
    }
    if (lane == 31) wsum[w] = sc;
    __syncthreads();
    if (t < 8) {
        int v = wsum[t];
        int s = v;
        #pragma unroll
        for (int off = 1; off < 8; off <<= 1) {
            int n = __shfl_up_sync(0xffu, s, off);
            if (t >= off) s += n;
        }
        woff[t] = s - v;
        if (t == 7) g_bsum[blk] = s;
    }
    __syncthreads();
    int excl = woff[w] + (sc - tot);
    if (base + 0 < nN) g_rowstart[base + 0] = excl;
    if (base + 1 < nN) g_rowstart[base + 1] = excl + i0;
    if (base + 2 < nN) g_rowstart[base + 2] = excl + i1;
    if (base + 3 < nN) g_rowstart[base + 3] = excl + i2;
}

// ---------------- scan phase 2 (fused tops): each block re-scans bsums ----
__global__ void scan_add_kernel(int nN, int nE, int nScanBlocks) {
    __shared__ int sboff[128];
    int t = threadIdx.x;
    if (t < 32) {
        int lane = t;
        int v0 = (lane      < nScanBlocks) ? g_bsum[lane]      : 0;
        int v1 = (lane + 32 < nScanBlocks) ? g_bsum[lane + 32] : 0;
        int v2 = (lane + 64 < nScanBlocks) ? g_bsum[lane + 64] : 0;
        int v3 = (lane + 96 < nScanBlocks) ? g_bsum[lane + 96] : 0;
        int s0 = v0, s1 = v1, s2 = v2, s3 = v3;
        #pragma unroll
        for (int off = 1; off < 32; off <<= 1) {
            int n0 = __shfl_up_sync(0xffffffffu, s0, off);
            int n1 = __shfl_up_sync(0xffffffffu, s1, off);
            int n2 = __shfl_up_sync(0xffffffffu, s2, off);
            int n3 = __shfl_up_sync(0xffffffffu, s3, off);
            if (lane >= off) { s0 += n0; s1 += n1; s2 += n2; s3 += n3; }
        }
        int t0 = __shfl_sync(0xffffffffu, s0, 31);
        int t1 = __shfl_sync(0xffffffffu, s1, 31);
        int t2 = __shfl_sync(0xffffffffu, s2, 31);
        sboff[lane]      = s0 - v0;
        sboff[lane + 32] = t0 + (s1 - v1);
        sboff[lane + 64] = t0 + t1 + (s2 - v2);
        sboff[lane + 96] = t0 + t1 + t2 + (s3 - v3);
    }
    __syncthreads();
    int i = blockIdx.x * blockDim.x + t;
    if (i < nN) {
        int s = g_rowstart[i] + sboff[i >> 10];
        g_rowstart[i] = s;
        g_cursor[i] = s;
    }
    if (i == 0) g_rowstart[nN] = nE;
}

// ---------------- CSR build: placement ----------------
__global__ void fill_kernel(const void* __restrict__ ei_v, int nE) {
    int e = blockIdx.x * blockDim.x + threadIdx.x;
    if (e >= nE) return;
    int src, dst;
    if (g_ei64) {
        const long long* ei = (const long long*)ei_v;
        src = (int)ei[e];
        dst = (int)ei[(long long)nE + e];
    } else {
        const int* ei = (const int*)ei_v;
        src = ei[e];
        dst = ei[nE + e];
    }
    int pos = atomicAdd(&g_cursor[dst], 1);
    g_srcs[pos] = src;
}

// ---------------- gather-mean (R7 fp32 form — proven wall, keep) ----------
__global__ void gather_kernel(const float* __restrict__ x, int nN, int fromH) {
    int gtid = blockIdx.x * blockDim.x + threadIdx.x;
    int node = gtid >> 5;
    int lane = gtid & 31;
    if (node >= nN) return;
    const float* base = fromH ? (const float*)g_h : x;
    int s = g_rowstart[node];
    int e = g_rowstart[node + 1];
    float ax = 0.f, ay = 0.f;

    for (int b = s; b < e; b += 32) {
        int cnt = min(32, e - b);
        int idxv = (lane < cnt) ? __ldg(&g_srcs[b + lane]) : 0;
        int j = 0;
        for (; j + 4 <= cnt; j += 4) {
            int a0 = __shfl_sync(0xffffffffu, idxv, j);
            int a1 = __shfl_sync(0xffffffffu, idxv, j + 1);
            int a2 = __shfl_sync(0xffffffffu, idxv, j + 2);
            int a3 = __shfl_sync(0xffffffffu, idxv, j + 3);
            float2 v0 = __ldg((const float2*)(base + (size_t)a0 * FEAT) + lane);
            float2 v1 = __ldg((const float2*)(base + (size_t)a1 * FEAT) + lane);
            float2 v2 = __ldg((const float2*)(base + (size_t)a2 * FEAT) + lane);
            float2 v3 = __ldg((const float2*)(base + (size_t)a3 * FEAT) + lane);
            ax += (v0.x + v1.x) + (v2.x + v3.x);
            ay += (v0.y + v1.y) + (v2.y + v3.y);
        }
        for (; j < cnt; j++) {
            int a0 = __shfl_sync(0xffffffffu, idxv, j);
            float2 v0 = __ldg((const float2*)(base + (size_t)a0 * FEAT) + lane);
            ax += v0.x; ay += v0.y;
        }
    }
    float inv = 1.0f / fmaxf((float)(e - s), 1.0f);
    reinterpret_cast<float2*>(g_S)[node * 32 + lane] = make_float2(ax * inv, ay * inv);
}

// ---------------- wmma tf32 fused layer GEMM (exact R11 form, occ=2) ------
// out = relu([S|X](tf32) @ [Wrel;Wroot](tf32) + b), fp32 accumulate.
// Block: 128 rows x 64 cols, 8 warps; warp w -> rows 16w..16w+15.
#define A_LDF 136
#define B_LDF 68
__global__ void __launch_bounds__(256, 2)
mma_layer(const float* __restrict__ Xin,
          const float* __restrict__ Wrel,
          const float* __restrict__ Wroot,
          const float* __restrict__ bias,
          float* __restrict__ out,
          int nRows) {
    extern __shared__ float dynf[];
    float* sA = dynf;                  // 128*136*4 = 69632B
    float* sB = dynf + 128 * A_LDF;    // 128*68*4  = 34816B
    float* stage = dynf;               // reused post-compute
    __shared__ float s_bias[64];

    int tid = threadIdx.x;
    int warp = tid >> 5;
    int rowBase = blockIdx.x * 128;

    if (tid < 64) s_bias[tid] = bias[tid];

    // B tile [k][n] (K=128 rows): tf32-rounded
    for (int i = tid; i < 128 * 64; i += 256) {
        int k = i >> 6, n = i & 63;
        float w = (k < 64) ? Wrel[k * 64 + n] : Wroot[(k - 64) * 64 + n];
        sB[k * B_LDF + n] = wmma::__float_to_tf32(w);
    }

    // A tile [r][k] (K=128): k<64 from S, k>=64 from X
    for (int i = tid; i < 128 * 64; i += 256) {
        int r = i >> 6, k = i & 63;
        int grow = rowBase + r;
        float vS = 0.f, vX = 0.f;
        if (grow < nRows) {
            vS = g_S[(size_t)grow * 64 + k];
            vX = Xin[(size_t)grow * 64 + k];
        }
        sA[r * A_LDF + k]      = wmma::__float_to_tf32(vS);
        sA[r * A_LDF + 64 + k] = wmma::__float_to_tf32(vX);
    }
    __syncthreads();

    wmma::fragment<wmma::accumulator, 16, 16, 8, float> acc[4];
    #pragma unroll
    for (int j = 0; j < 4; j++) wmma::fill_fragment(acc[j], 0.0f);

    #pragma unroll
    for (int ks = 0; ks < 16; ks++) {
        wmma::fragment<wmma::matrix_a, 16, 16, 8, wmma::precision::tf32, wmma::row_major> aF;
        wmma::load_matrix_sync(aF, sA + (warp * 16) * A_LDF + ks * 8, A_LDF);
        #pragma unroll
        for (int j = 0; j < 4; j++) {
            wmma::fragment<wmma::matrix_b, 16, 16, 8, wmma::precision::tf32, wmma::row_major> bF;
            wmma::load_matrix_sync(bF, sB + (ks * 8) * B_LDF + j * 16, B_LDF);
            wmma::mma_sync(acc[j], aF, bF, acc[j]);
        }
    }
    __syncthreads();

    #pragma unroll
    for (int j = 0; j < 4; j++)
        wmma::store_matrix_sync(stage + (warp * 16) * 68 + j * 16, acc[j], 68,
                                wmma::mem_row_major);
    __syncthreads();

    for (int i = tid; i < 128 * 64; i += 256) {
        int r = i >> 6, c = i & 63;
        int grow = rowBase + r;
        if (grow < nRows) {
            float v = stage[r * 68 + c] + s_bias[c];
            out[(size_t)grow * 64 + c] = fmaxf(v, 0.f);
        }
    }
}

// ---------------- head with fused pooling: one block per graph ------------
__device__ __forceinline__ long long batch_at(const void* b, int i, int is64) {
    return is64 ? ((const long long*)b)[i] : (long long)((const int*)b)[i];
}

__global__ void head_pool_kernel(const void* __restrict__ batch, int nRows,
                                 const float* __restrict__ Wh, const float* __restrict__ bh,
                                 const float* __restrict__ Wc, const float* __restrict__ bc,
                                 const float* __restrict__ Wo, const float* __restrict__ bo,
                                 float* __restrict__ out) {
    int g = blockIdx.x;
    int is64 = g_b64;
    int lo = 0, hi = nRows;
    while (lo < hi) { int m = (lo + hi) >> 1; if (batch_at(batch, m, is64) < g) lo = m + 1; else hi = m; }
    int start = lo;
    lo = 0; hi = nRows;
    while (lo < hi) { int m = (lo + hi) >> 1; if (batch_at(batch, m, is64) < g + 1) lo = m + 1; else hi = m; }
    int end = lo;

    int tid = threadIdx.x;
    int feat = tid & 63;
    int rl   = tid >> 6;

    __shared__ float sm[4][64];
    __shared__ float sp[64];
    __shared__ float sh[64];

    float s = 0.f;
    for (int r = start + rl; r < end; r += 4)
        s += g_h2[(long long)r * FEAT + feat];
    sm[rl][feat] = s;
    __syncthreads();
    if (rl == 0) {
        float tot = sm[0][feat] + sm[1][feat] + sm[2][feat] + sm[3][feat];
        sp[feat] = tot / fmaxf((float)(end - start), 1.0f);
    }
    __syncthreads();

    if (tid < 64) {
        int j = tid;
        float ah = bh[j], ac = bc[j];
        #pragma unroll 8
        for (int k = 0; k < 64; k++) {
            float p = sp[k];
            ah += p * Wh[k * 64 + j];
            ac += p * Wc[k * 64 + j];
        }
        sh[j] = ah;
        out[2048 + g * 64 + j] = ah;
        out[2048 + 4096 + g * 64 + j] = ac;
    }
    __syncthreads();

    if (tid < 32) {
        int lane = tid;
        float z = bo[lane];
        #pragma unroll 8
        for (int k = 0; k < 64; k++)
            z += sh[k] * Wo[k * 32 + lane];
        float m = z;
        #pragma unroll
        for (int off = 16; off > 0; off >>= 1)
            m = fmaxf(m, __shfl_xor_sync(0xffffffffu, m, off));
        float e = expf(z - m);
        #pragma unroll
        for (int off = 16; off > 0; off >>= 1)
            e += __shfl_xor_sync(0xffffffffu, e, off);
        out[g * 32 + lane] = z - m - logf(e);
    }
}

// ---------------- launch ----------------
extern "C" void kernel_launch(void* const* d_in, const int* in_sizes, int n_in,
                              void* d_out, int out_size) {
    const float* x     = (const float*)d_in[0];
    const void*  ei    = d_in[1];
    const void*  batch = d_in[2];
    const float* W1    = (const float*)d_in[3];
    const float* root1 = (const float*)d_in[4];
    const float* b1    = (const float*)d_in[5];
    const float* W2    = (const float*)d_in[6];
    const float* root2 = (const float*)d_in[7];
    const float* b2    = (const float*)d_in[8];
    const float* Wh    = (const float*)d_in[9];
    const float* bh    = (const float*)d_in[10];
    const float* Wc    = (const float*)d_in[11];
    const float* bc    = (const float*)d_in[12];
    const float* Wo    = (const float*)d_in[13];
    const float* bo    = (const float*)d_in[14];

    int nN = in_sizes[0] / FEAT;   // 100000
    int nE = in_sizes[1] / 2;      // 1600000

    int eBlocks = (nE + 255) / 256;
    int nBlocks = (nN + 255) / 256;
    int scanBlocks = (nN + 1023) / 1024;      // <=128
    int gatherBlocks = (nN * 32 + 255) / 256;
    int mmaBlocks = (nN + 127) / 128;
    size_t dynBytes = (size_t)(128 * A_LDF + 128 * B_LDF) * 4;   // 104448B

    float* h1 = nullptr; float* h2 = nullptr;
    cudaGetSymbolAddress((void**)&h1, g_h);
    cudaGetSymbolAddress((void**)&h2, g_h2);

    cudaFuncSetAttribute(mma_layer, cudaFuncAttributeMaxDynamicSharedMemorySize,
                         (int)dynBytes);

    // CSR build (scan_tops folded into scan_add)
    zero_detect_kernel<<<nBlocks, 256>>>(ei, batch, nE, nN);
    hist_kernel<<<eBlocks, 256>>>(ei, nE);
    scan_block_kernel<<<scanBlocks, 256>>>(nN);
    scan_add_kernel<<<nBlocks, 256>>>(nN, nE, scanBlocks);
    fill_kernel<<<eBlocks, 256>>>(ei, nE);

    // layer 1
    gather_kernel<<<gatherBlocks, 256>>>(x, nN, 0);
    mma_layer<<<mmaBlocks, 256, dynBytes>>>(x, W1, root1, b1, h1, nN);

    // layer 2
    gather_kernel<<<gatherBlocks, 256>>>(x, nN, 1);
    mma_layer<<<mmaBlocks, 256, dynBytes>>>(h1, W2, root2, b2, h2, nN);

    // pool + heads (fused)
    head_pool_kernel<<<N_GRAPHS, 256>>>(batch, nN, Wh, bh, Wc, bc, Wo, bo,
                                        (float*)d_out);
}